// round 2
// baseline (speedup 1.0000x reference)
#include <cuda_runtime.h>

// Problem constants
#define LL 256      // sequence length (Lx = Ly)
#define DD 20       // head size = input dim
#define NH 2        // heads
#define HD 40       // NH * DD
#define ROW (LL*DD) // 5120 floats per (set,set) tile

// Dynamic shared memory layout (floats):
//  sK   [256*40] = 10240
//  sV   [256*40] = 10240
//  sO   [256*40] = 10240  (holds x tile [0..5119] and y tile [5120..10239] during
//                          projection phase; reused for attention output O)
//  sWQ  [800], sWK [800], sWV [800], sWH [800]
#define SMEM_FLOATS (3*10240 + 4*800)

__global__ __launch_bounds__(512, 1)
void set_attn_kernel(const float* __restrict__ x, const float* __restrict__ y,
                     const float* __restrict__ WQ, const float* __restrict__ WK,
                     const float* __restrict__ WV, const float* __restrict__ WH,
                     float* __restrict__ out)
{
    extern __shared__ float sm[];
    float* sK  = sm;
    float* sV  = sm + 10240;
    float* sO  = sm + 20480;
    float* sWQ = sm + 30720;
    float* sWK = sWQ + 800;
    float* sWV = sWK + 800;
    float* sWH = sWV + 800;

    const int tid = threadIdx.x;
    const int b   = blockIdx.x;      // output tile (i, j)
    const int i   = b >> 5;
    const int j   = b & 31;

    // out[i][j] <- Q from x[i][j], K/V from y[j][i]
    const float* xb = x + (size_t)b * ROW;
    const float* yb = y + (size_t)(j * 32 + i) * ROW;

    // ---------------- Phase 1: stage tiles + weights into SMEM ----------------
    {
        const float4* x4 = (const float4*)xb;
        const float4* y4 = (const float4*)yb;
        float4* sx4 = (float4*)sO;            // x tile at sO[0..5119]
        float4* sy4 = (float4*)(sO + ROW);    // y tile at sO[5120..10239]
        #pragma unroll 1
        for (int t = tid; t < ROW/4; t += 512) { sx4[t] = x4[t]; sy4[t] = y4[t]; }
        #pragma unroll 1
        for (int t = tid; t < 800; t += 512) {
            sWQ[t] = WQ[t]; sWK[t] = WK[t]; sWV[t] = WV[t]; sWH[t] = WH[t];
        }
    }
    __syncthreads();

    const int qi = tid >> 1;   // query row (0..255)
    const int h  = tid & 1;    // head (0..1)

    // ---------------- Phase 2: projections ----------------
    // q (registers): q[d] = sum_e x[qi][e] * WQ[e][h*20+d]
    float q[DD];
    {
        const float* xr = sO + qi * DD;
        #pragma unroll
        for (int d = 0; d < DD; d++) q[d] = 0.f;
        #pragma unroll
        for (int e = 0; e < DD; e++) {
            const float xv = xr[e];
            const float* w = sWQ + e * HD + h * DD;
            #pragma unroll
            for (int d = 0; d < DD; d++) q[d] = fmaf(xv, w[d], q[d]);
        }
    }
    // K, V rows (SMEM): thread covers row qi, columns [h*20, h*20+20)
    {
        const float* yr = sO + ROW + qi * DD;
        float ka[DD], va[DD];
        #pragma unroll
        for (int d = 0; d < DD; d++) { ka[d] = 0.f; va[d] = 0.f; }
        #pragma unroll
        for (int e = 0; e < DD; e++) {
            const float yv = yr[e];
            const float* wk = sWK + e * HD + h * DD;
            const float* wv = sWV + e * HD + h * DD;
            #pragma unroll
            for (int d = 0; d < DD; d++) {
                ka[d] = fmaf(yv, wk[d], ka[d]);
                va[d] = fmaf(yv, wv[d], va[d]);
            }
        }
        #pragma unroll
        for (int d = 0; d < DD; d++) {
            sK[qi * HD + h * DD + d] = ka[d];
            sV[qi * HD + h * DD + d] = va[d];
        }
    }
    __syncthreads();

    // ---------------- Phase 3: attention (no max subtraction needed:
    // logit variance == 1 by construction, |logit| << 80, exp cannot overflow;
    // softmax is shift-invariant so this matches the reference to fp32 rounding,
    // and the +1e-10 epsilon difference is O(1e-10/sum) — far below tolerance).
    const float scale = 0.2236067977499789696f;  // 1/sqrt(20)
    float o[DD];
    #pragma unroll
    for (int d = 0; d < DD; d++) o[d] = 0.f;
    float ssum = 0.f;

    #pragma unroll 4
    for (int ky = 0; ky < LL; ky++) {
        const float4* kr = (const float4*)(sK + ky * HD + h * DD);
        float l = 0.f;
        #pragma unroll
        for (int d4 = 0; d4 < 5; d4++) {
            const float4 kv = kr[d4];
            l = fmaf(q[d4*4+0], kv.x, l);
            l = fmaf(q[d4*4+1], kv.y, l);
            l = fmaf(q[d4*4+2], kv.z, l);
            l = fmaf(q[d4*4+3], kv.w, l);
        }
        l *= scale;
        // custom zero-logit mask from the reference
        const float w = (l != 0.0f) ? __expf(l) : 0.0f;
        ssum += w;
        const float4* vr = (const float4*)(sV + ky * HD + h * DD);
        #pragma unroll
        for (int d4 = 0; d4 < 5; d4++) {
            const float4 vv = vr[d4];
            o[d4*4+0] = fmaf(w, vv.x, o[d4*4+0]);
            o[d4*4+1] = fmaf(w, vv.y, o[d4*4+1]);
            o[d4*4+2] = fmaf(w, vv.z, o[d4*4+2]);
            o[d4*4+3] = fmaf(w, vv.w, o[d4*4+3]);
        }
    }

    // normalize and park O in SMEM (x/y staging no longer needed; everything
    // reading sO happened before the phase-2 barrier)
    {
        const float inv = 1.0f / (ssum + 1e-10f);
        #pragma unroll
        for (int d = 0; d < DD; d++) sO[qi * HD + h * DD + d] = o[d] * inv;
    }
    __syncthreads();

    // ---------------- Phase 4: output projection ----------------
    // out[qi][dd] = sum_c O[qi][c] * WH[c][dd]; thread covers dd in [h*10, h*10+10)
    {
        float acc[10];
        #pragma unroll
        for (int t = 0; t < 10; t++) acc[t] = 0.f;
        const float* orow = sO + qi * HD;
        #pragma unroll
        for (int c = 0; c < HD; c++) {
            const float ov = orow[c];
            const float* wh = sWH + c * DD + h * 10;
            #pragma unroll
            for (int t = 0; t < 10; t++) acc[t] = fmaf(ov, wh[t], acc[t]);
        }
        float* og = out + (size_t)b * ROW + qi * DD + h * 10;
        #pragma unroll
        for (int t = 0; t < 10; t++) og[t] = acc[t];
    }
}

extern "C" void kernel_launch(void* const* d_in, const int* in_sizes, int n_in,
                              void* d_out, int out_size)
{
    const float* x  = (const float*)d_in[0];
    const float* y  = (const float*)d_in[1];
    const float* WQ = (const float*)d_in[2];
    const float* WK = (const float*)d_in[3];
    const float* WV = (const float*)d_in[4];
    const float* WH = (const float*)d_in[5];
    float* out = (float*)d_out;

    const int smem_bytes = SMEM_FLOATS * (int)sizeof(float);  // 135680
    cudaFuncSetAttribute(set_attn_kernel,
                         cudaFuncAttributeMaxDynamicSharedMemorySize, smem_bytes);
    set_attn_kernel<<<1024, 512, smem_bytes>>>(x, y, WQ, WK, WV, WH, out);
}

// round 4
// speedup vs baseline: 1.2492x; 1.2492x over previous
#include <cuda_runtime.h>

// Problem constants
#define LL 256      // sequence length
#define DD 20       // head size = input dim
#define NH 2        // heads
#define HD 40       // NH * DD
#define ROW (LL*DD) // 5120 floats per (set,set) tile

// SMEM (floats): sK [256*40]=10240, sV [256*40]=10240,
//                weights WQ|WK|WV|WH 4*800=3200
// O (stride 44, 256*44=11264 floats) is parked over sK/sV after the main loop.
#define SMEM_FLOATS (2*10240 + 4*800)

typedef unsigned long long u64;

__device__ __forceinline__ u64 pk2(float a, float b) {
    u64 r; asm("mov.b64 %0,{%1,%2};" : "=l"(r) : "f"(a), "f"(b)); return r;
}
__device__ __forceinline__ void upk2(u64 v, float& a, float& b) {
    asm("mov.b64 {%0,%1},%2;" : "=f"(a), "=f"(b) : "l"(v));
}
__device__ __forceinline__ u64 fma2(u64 a, u64 b, u64 c) {
    u64 d; asm("fma.rn.f32x2 %0,%1,%2,%3;" : "=l"(d) : "l"(a), "l"(b), "l"(c)); return d;
}
__device__ __forceinline__ u64 mul2(u64 a, u64 b) {
    u64 d; asm("mul.rn.f32x2 %0,%1,%2;" : "=l"(d) : "l"(a), "l"(b)); return d;
}
__device__ __forceinline__ u64 add2(u64 a, u64 b) {
    u64 d; asm("add.rn.f32x2 %0,%1,%2;" : "=l"(d) : "l"(a), "l"(b)); return d;
}
__device__ __forceinline__ float ex2a(float x) {
    float r; asm("ex2.approx.ftz.f32 %0,%1;" : "=f"(r) : "f"(x)); return r;
}

__global__ __launch_bounds__(512, 1)
void set_attn_kernel(const float* __restrict__ x, const float* __restrict__ y,
                     const float* __restrict__ WQ, const float* __restrict__ WK,
                     const float* __restrict__ WV, const float* __restrict__ WH,
                     float* __restrict__ out)
{
    extern __shared__ float sm[];
    float* sK = sm;
    float* sV = sm + 10240;
    float* sW = sm + 20480;   // WQ[0,800) WK[800,1600) WV[1600,2400) WH[2400,3200)

    const int tid  = threadIdx.x;
    const int b    = blockIdx.x;
    const int i    = b >> 5;
    const int j    = b & 31;
    const int warp = tid >> 5;
    const int lane = tid & 31;
    // single-head warps: all lanes of a warp share h -> K/V row loads are
    // 1-line broadcasts (1 wavefront per LDS.128)
    const int h  = warp & 1;
    const int qi = ((warp >> 1) << 5) | lane;

    // ---------------- stage weights ----------------
    #pragma unroll 1
    for (int t = tid; t < 800; t += 512) {
        sW[t]        = WQ[t];
        sW[800 + t]  = WK[t];
        sW[1600 + t] = WV[t];
        sW[2400 + t] = WH[t];
    }
    __syncthreads();

    // ---------------- projections (3 low-register passes) ----------------
    // y row for K/V, x row for Q (direct from GMEM; coalesced float4)
    const float* xr = x + (size_t)b * ROW + qi * DD;
    const float* yr = y + (size_t)(j * 32 + i) * ROW + qi * DD;

    float yv[DD];
    {
        #pragma unroll
        for (int t = 0; t < 5; t++) {
            const float4 v4 = ((const float4*)yr)[t];
            yv[4*t+0] = v4.x; yv[4*t+1] = v4.y; yv[4*t+2] = v4.z; yv[4*t+3] = v4.w;
        }
    }

    // K pass
    {
        u64 k2[10];
        #pragma unroll
        for (int d = 0; d < 10; d++) k2[d] = 0ull;
        const ulonglong2* wKb = (const ulonglong2*)(sW + 800) + h * 5;
        #pragma unroll
        for (int e = 0; e < DD; e++) {
            const u64 yv2 = pk2(yv[e], yv[e]);
            const ulonglong2* w = wKb + e * 10;
            #pragma unroll
            for (int p = 0; p < 5; p++) {
                const ulonglong2 wp = w[p];
                k2[2*p+0] = fma2(yv2, wp.x, k2[2*p+0]);
                k2[2*p+1] = fma2(yv2, wp.y, k2[2*p+1]);
            }
        }
        ulonglong2* skp = (ulonglong2*)sK + qi * 10 + h * 5;
        #pragma unroll
        for (int p = 0; p < 5; p++) skp[p] = make_ulonglong2(k2[2*p], k2[2*p+1]);
    }
    // V pass
    {
        u64 v2[10];
        #pragma unroll
        for (int d = 0; d < 10; d++) v2[d] = 0ull;
        const ulonglong2* wVb = (const ulonglong2*)(sW + 1600) + h * 5;
        #pragma unroll
        for (int e = 0; e < DD; e++) {
            const u64 yv2 = pk2(yv[e], yv[e]);
            const ulonglong2* w = wVb + e * 10;
            #pragma unroll
            for (int p = 0; p < 5; p++) {
                const ulonglong2 wp = w[p];
                v2[2*p+0] = fma2(yv2, wp.x, v2[2*p+0]);
                v2[2*p+1] = fma2(yv2, wp.y, v2[2*p+1]);
            }
        }
        ulonglong2* svp = (ulonglong2*)sV + qi * 10 + h * 5;
        #pragma unroll
        for (int p = 0; p < 5; p++) svp[p] = make_ulonglong2(v2[2*p], v2[2*p+1]);
    }
    // Q pass (stays in registers)
    u64 q2[10];
    {
        #pragma unroll
        for (int d = 0; d < 10; d++) q2[d] = 0ull;
        float xv[DD];
        #pragma unroll
        for (int t = 0; t < 5; t++) {
            const float4 v4 = ((const float4*)xr)[t];
            xv[4*t+0] = v4.x; xv[4*t+1] = v4.y; xv[4*t+2] = v4.z; xv[4*t+3] = v4.w;
        }
        const ulonglong2* wQb = (const ulonglong2*)sW + h * 5;
        #pragma unroll
        for (int e = 0; e < DD; e++) {
            const u64 xv2 = pk2(xv[e], xv[e]);
            const ulonglong2* w = wQb + e * 10;
            #pragma unroll
            for (int p = 0; p < 5; p++) {
                const ulonglong2 wp = w[p];
                q2[2*p+0] = fma2(xv2, wp.x, q2[2*p+0]);
                q2[2*p+1] = fma2(xv2, wp.y, q2[2*p+1]);
            }
        }
    }
    __syncthreads();

    // ---------------- attention main loop ----------------
    // No max subtraction needed: logit variance == 1 by construction, exp can't
    // overflow; softmax is shift-invariant (matches ref to fp32 rounding).
    const float C = 0.22360679774997896f * 1.4426950408889634f; // scale * log2(e)
    u64 o2[10];
    #pragma unroll
    for (int d = 0; d < 10; d++) o2[d] = 0ull;
    float ssum = 0.f;

    const ulonglong2* kb = (const ulonglong2*)sK + h * 5;
    const ulonglong2* vb = (const ulonglong2*)sV + h * 5;

    #pragma unroll 2
    for (int ky = 0; ky < LL; ky++) {
        const ulonglong2* kr = kb + ky * 10;
        const ulonglong2 ka = kr[0], k1 = kr[1], kc = kr[2], kd = kr[3], ke = kr[4];
        u64 la = mul2(q2[0], ka.x);
        u64 lb = mul2(q2[1], ka.y);
        la = fma2(q2[2], k1.x, la);  lb = fma2(q2[3], k1.y, lb);
        la = fma2(q2[4], kc.x, la);  lb = fma2(q2[5], kc.y, lb);
        la = fma2(q2[6], kd.x, la);  lb = fma2(q2[7], kd.y, lb);
        la = fma2(q2[8], ke.x, la);  lb = fma2(q2[9], ke.y, lb);
        la = add2(la, lb);
        float l0, l1; upk2(la, l0, l1);
        const float l = l0 + l1;                 // raw dot (mask is scale-invariant)
        float w = ex2a(l * C);
        w = (l != 0.0f) ? w : 0.0f;              // reference's zero-logit mask
        ssum += w;
        const u64 w2 = pk2(w, w);
        const ulonglong2* vr = vb + ky * 10;
        const ulonglong2 va = vr[0], v1 = vr[1], vc = vr[2], vd = vr[3], ve = vr[4];
        o2[0] = fma2(w2, va.x, o2[0]);  o2[1] = fma2(w2, va.y, o2[1]);
        o2[2] = fma2(w2, v1.x, o2[2]);  o2[3] = fma2(w2, v1.y, o2[3]);
        o2[4] = fma2(w2, vc.x, o2[4]);  o2[5] = fma2(w2, vc.y, o2[5]);
        o2[6] = fma2(w2, vd.x, o2[6]);  o2[7] = fma2(w2, vd.y, o2[7]);
        o2[8] = fma2(w2, ve.x, o2[8]);  o2[9] = fma2(w2, ve.y, o2[9]);
    }

    // ---------------- normalize + park O (stride 44 to dodge bank conflicts) ----
    const float inv = 1.0f / (ssum + 1e-10f);
    __syncthreads();   // everyone done reading sK/sV
    {
        float4* orow = (float4*)(sm + qi * 44 + h * DD);
        #pragma unroll
        for (int p = 0; p < 5; p++) {
            float a0, a1, a2, a3;
            upk2(o2[2*p],   a0, a1);
            upk2(o2[2*p+1], a2, a3);
            orow[p] = make_float4(a0 * inv, a1 * inv, a2 * inv, a3 * inv);
        }
    }
    __syncthreads();

    // ---------------- output projection: out[qi][h*10 .. h*10+10) ----------------
    {
        u64 acc[5];
        #pragma unroll
        for (int p = 0; p < 5; p++) acc[p] = 0ull;
        const float4* orow = (const float4*)(sm + qi * 44);
        const ulonglong2* wHb = (const ulonglong2*)(sW + 2400) + h * 2;  // h*10 floats = h*2 u64... (h*10*4B=40B) -> not 16B aligned for h=1!
        // h*10 floats = 40B offset for h=1: NOT ulonglong2-aligned. Use u64 granularity instead.
        const u64* wHb64 = (const u64*)(sW + 2400) + h * 5;
        #pragma unroll
        for (int c4 = 0; c4 < 10; c4++) {
            const float4 ov4 = orow[c4];
            const float ov[4] = {ov4.x, ov4.y, ov4.z, ov4.w};
            #pragma unroll
            for (int u = 0; u < 4; u++) {
                const int c = c4 * 4 + u;
                const u64 ov2 = pk2(ov[u], ov[u]);
                const u64* wr = wHb64 + c * 10;
                #pragma unroll
                for (int p = 0; p < 5; p++) acc[p] = fma2(ov2, wr[p], acc[p]);
            }
        }
        float* og = out + (size_t)b * ROW + qi * DD + h * 10;
        #pragma unroll
        for (int p = 0; p < 5; p++) {
            float a0, a1; upk2(acc[p], a0, a1);
            ((float2*)og)[p] = make_float2(a0, a1);
        }
    }
}

extern "C" void kernel_launch(void* const* d_in, const int* in_sizes, int n_in,
                              void* d_out, int out_size)
{
    const float* x  = (const float*)d_in[0];
    const float* y  = (const float*)d_in[1];
    const float* WQ = (const float*)d_in[2];
    const float* WK = (const float*)d_in[3];
    const float* WV = (const float*)d_in[4];
    const float* WH = (const float*)d_in[5];
    float* out = (float*)d_out;

    const int smem_bytes = SMEM_FLOATS * (int)sizeof(float);  // 94720
    cudaFuncSetAttribute(set_attn_kernel,
                         cudaFuncAttributeMaxDynamicSharedMemorySize, smem_bytes);
    set_attn_kernel<<<1024, 512, smem_bytes>>>(x, y, WQ, WK, WV, WH, out);
}

// round 7
// speedup vs baseline: 1.3874x; 1.1106x over previous
#include <cuda_runtime.h>

// Problem constants
#define LL 256      // sequence length
#define DD 20       // head size = input dim
#define NH 2        // heads
#define HD 40       // NH * DD
#define ROW (LL*DD) // 5120 floats per (set,set) tile

// SMEM (floats): sK [256*40]=10240, sV [256*40]=10240, weights 4*800=3200
// O (stride 44, 256*44=11264 floats) is parked over sK/sV after the main loop.
#define SMEM_FLOATS (2*10240 + 4*800)

typedef unsigned long long u64;

__device__ __forceinline__ u64 pk2(float a, float b) {
    u64 r; asm("mov.b64 %0,{%1,%2};" : "=l"(r) : "f"(a), "f"(b)); return r;
}
__device__ __forceinline__ void upk2(u64 v, float& a, float& b) {
    asm("mov.b64 {%0,%1},%2;" : "=f"(a), "=f"(b) : "l"(v));
}
__device__ __forceinline__ u64 fma2(u64 a, u64 b, u64 c) {
    u64 d; asm("fma.rn.f32x2 %0,%1,%2,%3;" : "=l"(d) : "l"(a), "l"(b), "l"(c)); return d;
}
__device__ __forceinline__ u64 mul2(u64 a, u64 b) {
    u64 d; asm("mul.rn.f32x2 %0,%1,%2;" : "=l"(d) : "l"(a), "l"(b)); return d;
}
__device__ __forceinline__ u64 add2(u64 a, u64 b) {
    u64 d; asm("add.rn.f32x2 %0,%1,%2;" : "=l"(d) : "l"(a), "l"(b)); return d;
}
__device__ __forceinline__ float ex2a(float x) {
    float r; asm("ex2.approx.ftz.f32 %0,%1;" : "=f"(r) : "f"(x)); return r;
}

__global__ __launch_bounds__(256, 1)
void set_attn_kernel(const float* __restrict__ x, const float* __restrict__ y,
                     const float* __restrict__ WQ, const float* __restrict__ WK,
                     const float* __restrict__ WV, const float* __restrict__ WH,
                     float* __restrict__ out)
{
    extern __shared__ float sm[];
    float* sK = sm;
    float* sV = sm + 10240;
    float* sW = sm + 20480;   // WQ[0,800) WK[800,1600) WV[1600,2400) WH[2400,3200)

    const int tid  = threadIdx.x;
    const int b    = blockIdx.x;
    const int i    = b >> 5;
    const int j    = b & 31;
    const int warp = tid >> 5;
    const int lane = tid & 31;
    // 8 warps: h = warp&1 (whole warp one head -> broadcast K/V loads),
    // g = warp>>1 selects a 64-query stripe; each thread owns 2 queries.
    const int h  = warp & 1;
    const int g  = warp >> 1;
    const int qa = (g << 6) | lane;       // query row A
    const int qb = qa + 32;               // query row B

    // ---------------- stage weights ----------------
    #pragma unroll 1
    for (int t = tid; t < 800; t += 256) {
        sW[t]        = WQ[t];
        sW[800 + t]  = WK[t];
        sW[1600 + t] = WV[t];
        sW[2400 + t] = WH[t];
    }
    __syncthreads();

    const float* xbase = x + (size_t)b * ROW;
    const float* ybase = y + (size_t)(j * 32 + i) * ROW;

    // ---------------- K/V projection (rows qa, qb; head h) ----------------
    #pragma unroll
    for (int r = 0; r < 2; r++) {
        const int qi = r ? qb : qa;
        float yv[DD];
        #pragma unroll
        for (int t = 0; t < 5; t++) {
            const float4 v4 = ((const float4*)(ybase + qi * DD))[t];
            yv[4*t+0] = v4.x; yv[4*t+1] = v4.y; yv[4*t+2] = v4.z; yv[4*t+3] = v4.w;
        }
        // K pass
        {
            u64 k2[10];
            #pragma unroll
            for (int d = 0; d < 10; d++) k2[d] = 0ull;
            const ulonglong2* wKb = (const ulonglong2*)(sW + 800) + h * 5;
            #pragma unroll
            for (int e = 0; e < DD; e++) {
                const u64 yv2 = pk2(yv[e], yv[e]);
                const ulonglong2* w = wKb + e * 10;
                #pragma unroll
                for (int p = 0; p < 5; p++) {
                    const ulonglong2 wp = w[p];
                    k2[2*p+0] = fma2(yv2, wp.x, k2[2*p+0]);
                    k2[2*p+1] = fma2(yv2, wp.y, k2[2*p+1]);
                }
            }
            ulonglong2* skp = (ulonglong2*)sK + qi * 10 + h * 5;
            #pragma unroll
            for (int p = 0; p < 5; p++) skp[p] = make_ulonglong2(k2[2*p], k2[2*p+1]);
        }
        // V pass
        {
            u64 v2[10];
            #pragma unroll
            for (int d = 0; d < 10; d++) v2[d] = 0ull;
            const ulonglong2* wVb = (const ulonglong2*)(sW + 1600) + h * 5;
            #pragma unroll
            for (int e = 0; e < DD; e++) {
                const u64 yv2 = pk2(yv[e], yv[e]);
                const ulonglong2* w = wVb + e * 10;
                #pragma unroll
                for (int p = 0; p < 5; p++) {
                    const ulonglong2 wp = w[p];
                    v2[2*p+0] = fma2(yv2, wp.x, v2[2*p+0]);
                    v2[2*p+1] = fma2(yv2, wp.y, v2[2*p+1]);
                }
            }
            ulonglong2* svp = (ulonglong2*)sV + qi * 10 + h * 5;
            #pragma unroll
            for (int p = 0; p < 5; p++) svp[p] = make_ulonglong2(v2[2*p], v2[2*p+1]);
        }
    }

    // ---------------- Q projection (2 queries, kept in registers) ----------------
    u64 qA[10], qB[10];
    #pragma unroll
    for (int r = 0; r < 2; r++) {
        const int qi = r ? qb : qa;
        u64* q2 = r ? qB : qA;
        #pragma unroll
        for (int d = 0; d < 10; d++) q2[d] = 0ull;
        float xv[DD];
        #pragma unroll
        for (int t = 0; t < 5; t++) {
            const float4 v4 = ((const float4*)(xbase + qi * DD))[t];
            xv[4*t+0] = v4.x; xv[4*t+1] = v4.y; xv[4*t+2] = v4.z; xv[4*t+3] = v4.w;
        }
        const ulonglong2* wQb = (const ulonglong2*)sW + h * 5;
        #pragma unroll
        for (int e = 0; e < DD; e++) {
            const u64 xv2 = pk2(xv[e], xv[e]);
            const ulonglong2* w = wQb + e * 10;
            #pragma unroll
            for (int p = 0; p < 5; p++) {
                const ulonglong2 wp = w[p];
                q2[2*p+0] = fma2(xv2, wp.x, q2[2*p+0]);
                q2[2*p+1] = fma2(xv2, wp.y, q2[2*p+1]);
            }
        }
    }
    __syncthreads();

    // ---------------- attention main loop (2 queries share each K/V load) ------
    // No max subtraction needed: logit variance == 1 by construction, exp can't
    // overflow; softmax is shift-invariant (matches ref to fp32 rounding).
    const float C = 0.22360679774997896f * 1.4426950408889634f; // scale * log2(e)
    u64 oA[10], oB[10];
    #pragma unroll
    for (int d = 0; d < 10; d++) { oA[d] = 0ull; oB[d] = 0ull; }
    float ssA = 0.f, ssB = 0.f;

    const ulonglong2* kb = (const ulonglong2*)sK + h * 5;
    const ulonglong2* vb = (const ulonglong2*)sV + h * 5;

    #pragma unroll 2
    for (int ky = 0; ky < LL; ky++) {
        const ulonglong2* kr = kb + ky * 10;
        const ulonglong2 k0 = kr[0], k1 = kr[1], k2 = kr[2], k3 = kr[3], k4 = kr[4];

        u64 a0 = mul2(qA[0], k0.x);          u64 a1 = mul2(qA[1], k0.y);
        u64 b0 = mul2(qB[0], k0.x);          u64 b1 = mul2(qB[1], k0.y);
        a0 = fma2(qA[2], k1.x, a0);          a1 = fma2(qA[3], k1.y, a1);
        b0 = fma2(qB[2], k1.x, b0);          b1 = fma2(qB[3], k1.y, b1);
        a0 = fma2(qA[4], k2.x, a0);          a1 = fma2(qA[5], k2.y, a1);
        b0 = fma2(qB[4], k2.x, b0);          b1 = fma2(qB[5], k2.y, b1);
        a0 = fma2(qA[6], k3.x, a0);          a1 = fma2(qA[7], k3.y, a1);
        b0 = fma2(qB[6], k3.x, b0);          b1 = fma2(qB[7], k3.y, b1);
        a0 = fma2(qA[8], k4.x, a0);          a1 = fma2(qA[9], k4.y, a1);
        b0 = fma2(qB[8], k4.x, b0);          b1 = fma2(qB[9], k4.y, b1);
        a0 = add2(a0, a1);                   b0 = add2(b0, b1);

        float la0, la1, lb0, lb1;
        upk2(a0, la0, la1);                  upk2(b0, lb0, lb1);
        const float lA = la0 + la1;          const float lB = lb0 + lb1;
        float wA = ex2a(lA * C);             float wB = ex2a(lB * C);
        wA = (lA != 0.0f) ? wA : 0.0f;       wB = (lB != 0.0f) ? wB : 0.0f;
        ssA += wA;                           ssB += wB;
        const u64 wA2 = pk2(wA, wA);         const u64 wB2 = pk2(wB, wB);

        const ulonglong2* vr = vb + ky * 10;
        const ulonglong2 v0 = vr[0], v1 = vr[1], v2 = vr[2], v3 = vr[3], v4 = vr[4];
        oA[0] = fma2(wA2, v0.x, oA[0]);  oA[1] = fma2(wA2, v0.y, oA[1]);
        oB[0] = fma2(wB2, v0.x, oB[0]);  oB[1] = fma2(wB2, v0.y, oB[1]);
        oA[2] = fma2(wA2, v1.x, oA[2]);  oA[3] = fma2(wA2, v1.y, oA[3]);
        oB[2] = fma2(wB2, v1.x, oB[2]);  oB[3] = fma2(wB2, v1.y, oB[3]);
        oA[4] = fma2(wA2, v2.x, oA[4]);  oA[5] = fma2(wA2, v2.y, oA[5]);
        oB[4] = fma2(wB2, v2.x, oB[4]);  oB[5] = fma2(wB2, v2.y, oB[5]);
        oA[6] = fma2(wA2, v3.x, oA[6]);  oA[7] = fma2(wA2, v3.y, oA[7]);
        oB[6] = fma2(wB2, v3.x, oB[6]);  oB[7] = fma2(wB2, v3.y, oB[7]);
        oA[8] = fma2(wA2, v4.x, oA[8]);  oA[9] = fma2(wA2, v4.y, oA[9]);
        oB[8] = fma2(wB2, v4.x, oB[8]);  oB[9] = fma2(wB2, v4.y, oB[9]);
    }

    // ---------------- normalize + park O (stride 44 dodges bank conflicts) -----
    const float invA = 1.0f / (ssA + 1e-10f);
    const float invB = 1.0f / (ssB + 1e-10f);
    __syncthreads();   // everyone done reading sK/sV
    #pragma unroll
    for (int r = 0; r < 2; r++) {
        const int qi = r ? qb : qa;
        const u64* o2 = r ? oB : oA;
        const float inv = r ? invB : invA;
        float4* orow = (float4*)(sm + qi * 44 + h * DD);
        #pragma unroll
        for (int p = 0; p < 5; p++) {
            float c0, c1, c2, c3;
            upk2(o2[2*p],   c0, c1);
            upk2(o2[2*p+1], c2, c3);
            orow[p] = make_float4(c0 * inv, c1 * inv, c2 * inv, c3 * inv);
        }
    }
    __syncthreads();

    // ---------------- output projection: rows {qa,qb}, cols [h*10, h*10+10) ----
    #pragma unroll
    for (int r = 0; r < 2; r++) {
        const int qi = r ? qb : qa;
        u64 acc[5];
        #pragma unroll
        for (int p = 0; p < 5; p++) acc[p] = 0ull;
        const float4* orow = (const float4*)(sm + qi * 44);
        const u64* wHb64 = (const u64*)(sW + 2400) + h * 5;  // h*10 floats
        #pragma unroll
        for (int c4 = 0; c4 < 10; c4++) {
            const float4 ov4 = orow[c4];
            const float ov[4] = {ov4.x, ov4.y, ov4.z, ov4.w};
            #pragma unroll
            for (int u = 0; u < 4; u++) {
                const int c = c4 * 4 + u;
                const u64 ov2 = pk2(ov[u], ov[u]);
                const u64* wr = wHb64 + c * 10;
                #pragma unroll
                for (int p = 0; p < 5; p++) acc[p] = fma2(ov2, wr[p], acc[p]);
            }
        }
        float* og = out + (size_t)b * ROW + qi * DD + h * 10;
        #pragma unroll
        for (int p = 0; p < 5; p++) {
            float c0, c1; upk2(acc[p], c0, c1);
            ((float2*)og)[p] = make_float2(c0, c1);
        }
    }
}

extern "C" void kernel_launch(void* const* d_in, const int* in_sizes, int n_in,
                              void* d_out, int out_size)
{
    const float* x  = (const float*)d_in[0];
    const float* y  = (const float*)d_in[1];
    const float* WQ = (const float*)d_in[2];
    const float* WK = (const float*)d_in[3];
    const float* WV = (const float*)d_in[4];
    const float* WH = (const float*)d_in[5];
    float* out = (float*)d_out;

    const int smem_bytes = SMEM_FLOATS * (int)sizeof(float);  // 94720
    cudaFuncSetAttribute(set_attn_kernel,
                         cudaFuncAttributeMaxDynamicSharedMemorySize, smem_bytes);
    set_attn_kernel<<<1024, 256, smem_bytes>>>(x, y, WQ, WK, WV, WH, out);
}